// round 9
// baseline (speedup 1.0000x reference)
#include <cuda_runtime.h>
#include <math.h>
#include <stdint.h>

#define TT 512
#define BB 64
#define DD 512
#define HH 512
#define GG 2048
#define KTOT 1024

typedef unsigned long long u64;

// ---------------- device scratch ----------------
__device__ float g_W[(size_t)GG * KTOT];          // 8 MB normalized weights
// zx layout: [t][cb 32][bg 4][64 rows (gate*16+cloc)][16 b]
__device__ float g_zx[(size_t)TT * 32 * 4 * 64 * 16];
__device__ float g_hG[4][2][512 * 16];            // [group][parity][col*16+b]
__device__ unsigned g_flag[4][32][8];             // [group][cb][pad] step counter
__device__ float g_outs[(size_t)TT * 4 * 32 * 256]; // coalesced out scratch

// ---------------- f32x2 helpers ----------------
__device__ __forceinline__ u64 pack2(float x, float y) {
    u64 r; asm("mov.b64 %0, {%1, %2};" : "=l"(r) : "f"(x), "f"(y)); return r;
}
__device__ __forceinline__ void fma2(u64& d, u64 a, u64 b) {
    asm("fma.rn.f32x2 %0, %1, %2, %0;" : "+l"(d) : "l"(a), "l"(b));
}
__device__ __forceinline__ float2 unpack2(u64 v) {
    float2 f; asm("mov.b64 {%0, %1}, %2;" : "=f"(f.x), "=f"(f.y) : "l"(v)); return f;
}

// L2-only 16B load (bypasses L1 -> sees peer CTAs' writes)
__device__ __forceinline__ ulonglong2 ldcg_u64x2(const void* p) {
    ulonglong2 r;
    asm volatile("ld.global.cg.v2.u64 {%0, %1}, [%2];"
                 : "=l"(r.x), "=l"(r.y) : "l"(p));
    return r;
}

// ---------------- mbarrier + bulk-async (zx prefetch only) ----------------
__device__ __forceinline__ unsigned smem_u32(const void* p) {
    return (unsigned)__cvta_generic_to_shared(p);
}
__device__ __forceinline__ void mbar_init(unsigned mbar, unsigned count) {
    asm volatile("mbarrier.init.shared.b64 [%0], %1;" :: "r"(mbar), "r"(count) : "memory");
}
__device__ __forceinline__ void mbar_expect_tx(unsigned mbar, unsigned bytes) {
    asm volatile("mbarrier.arrive.expect_tx.shared.b64 _, [%0], %1;"
                 :: "r"(mbar), "r"(bytes) : "memory");
}
__device__ __forceinline__ void mbar_wait(unsigned mbar, unsigned parity) {
    unsigned done;
    asm volatile(
        "{\n\t.reg .pred p;\n\t"
        "mbarrier.try_wait.parity.acquire.cta.shared::cta.b64 p, [%1], %2;\n\t"
        "selp.b32 %0, 1, 0, p;\n\t}"
        : "=r"(done) : "r"(mbar), "r"(parity) : "memory");
    if (!done) {
        asm volatile(
            "{\n\t.reg .pred P1;\n\t"
            "WL_%=:\n\t"
            "mbarrier.try_wait.parity.acquire.cta.shared::cta.b64 P1, [%0], %1, 0x989680;\n\t"
            "@P1 bra.uni WD_%=;\n\t"
            "bra.uni WL_%=;\n\t"
            "WD_%=:\n\t}"
            :: "r"(mbar), "r"(parity) : "memory");
    }
}
__device__ __forceinline__ void bulk_g2s(unsigned smem_dst, const void* gsrc,
                                         unsigned bytes, unsigned mbar) {
    asm volatile(
        "cp.async.bulk.shared::cluster.global.mbarrier::complete_tx::bytes [%0], [%1], %2, [%3];"
        :: "r"(smem_dst), "l"(gsrc), "r"(bytes), "r"(mbar) : "memory");
}
__device__ __forceinline__ void fence_proxy_async_cta() {
    asm volatile("fence.proxy.async.shared::cta;" ::: "memory");
}
__device__ __forceinline__ unsigned ld_acq(const unsigned* p) {
    unsigned v;
    asm volatile("ld.acquire.gpu.u32 %0, [%1];" : "=r"(v) : "l"(p) : "memory");
    return v;
}

__device__ __forceinline__ float sigf(float x) { return 1.0f / (1.0f + expf(-x)); }

// ============================================================================
// Phase 0: per-replay init — zero flags + h buffers (ordered before recur)
// ============================================================================
__global__ __launch_bounds__(256) void qlstm_init() {
    int tid = blockIdx.x * 256 + threadIdx.x;   // grid 32 x 256 = 8192
    if (tid < 4 * 32 * 8) ((unsigned*)g_flag)[tid] = 0;
    float* hflat = (float*)g_hG;                // 4*2*8192 = 65536 floats
    #pragma unroll
    for (int u = 0; u < 8; u++) hflat[tid + u * 8192] = 0.0f;
}

// ============================================================================
// Phase 1: weight norm
// ============================================================================
__global__ __launch_bounds__(256) void qlstm_wnorm(const float* __restrict__ v,
                                                   const float* __restrict__ g) {
    int r = blockIdx.x;
    const float* vr = v + (size_t)r * KTOT;
    float s = 0.0f;
    for (int k = threadIdx.x; k < KTOT; k += 256) { float x = vr[k]; s += x * x; }
    __shared__ float red[256];
    red[threadIdx.x] = s;
    __syncthreads();
    for (int off = 128; off > 0; off >>= 1) {
        if (threadIdx.x < off) red[threadIdx.x] += red[threadIdx.x + off];
        __syncthreads();
    }
    float scale = g[r] * rsqrtf(red[0]);
    for (int k = threadIdx.x; k < KTOT; k += 256)
        g_W[(size_t)r * KTOT + k] = vr[k] * scale;
}

// ============================================================================
// Phase 2: zx = X @ Wx^T + bias, grouped layout. (unchanged from R8)
// ============================================================================
#define AST_PAD 132
#define BSS_PAD 132

__global__ __launch_bounds__(256) void qlstm_gemm_x(const float* __restrict__ X,
                                                    const float* __restrict__ bias) {
    __shared__ float Ast[16 * AST_PAD];
    __shared__ float Bs[16 * BSS_PAD];

    const int rt  = blockIdx.x * 128;
    const int nt  = blockIdx.y * 128;
    const int tid = threadIdx.x;
    const int rg  = tid >> 4;
    const int ng  = tid & 15;
    const int r0  = rg * 8;
    const int n0  = ng * 8;

    u64 acc[8][4];
    #pragma unroll
    for (int i = 0; i < 8; i++)
        #pragma unroll
        for (int j = 0; j < 4; j++) acc[i][j] = 0ULL;

    for (int kt = 0; kt < DD; kt += 16) {
        __syncthreads();
        #pragma unroll
        for (int u = 0; u < 2; u++) {
            int idx = tid + u * 256;
            int r = idx >> 2, kq = (idx & 3) << 2;
            float4 va = *(const float4*)(g_W + (size_t)(rt + r) * KTOT + kt + kq);
            Ast[(kq + 0) * AST_PAD + r] = va.x;
            Ast[(kq + 1) * AST_PAD + r] = va.y;
            Ast[(kq + 2) * AST_PAD + r] = va.z;
            Ast[(kq + 3) * AST_PAD + r] = va.w;
        }
        #pragma unroll
        for (int u = 0; u < 2; u++) {
            int idx = tid + u * 256;
            int n = idx >> 2, kq = (idx & 3) << 2;
            float4 vb = *(const float4*)(X + (size_t)(nt + n) * DD + kt + kq);
            Bs[(kq + 0) * BSS_PAD + n] = vb.x;
            Bs[(kq + 1) * BSS_PAD + n] = vb.y;
            Bs[(kq + 2) * BSS_PAD + n] = vb.z;
            Bs[(kq + 3) * BSS_PAD + n] = vb.w;
        }
        __syncthreads();

        #pragma unroll
        for (int kk = 0; kk < 16; kk++) {
            ulonglong2 b01 = *(const ulonglong2*)&Bs[kk * BSS_PAD + n0];
            ulonglong2 b23 = *(const ulonglong2*)&Bs[kk * BSS_PAD + n0 + 4];
            float4 w0 = *(const float4*)&Ast[kk * AST_PAD + r0];
            float4 w1 = *(const float4*)&Ast[kk * AST_PAD + r0 + 4];
            float wv[8] = {w0.x, w0.y, w0.z, w0.w, w1.x, w1.y, w1.z, w1.w};
            #pragma unroll
            for (int i = 0; i < 8; i++) {
                u64 wd = pack2(wv[i], wv[i]);
                fma2(acc[i][0], wd, b01.x); fma2(acc[i][1], wd, b01.y);
                fma2(acc[i][2], wd, b23.x); fma2(acc[i][3], wd, b23.y);
            }
        }
    }

    const int t  = blockIdx.y * 2 + (n0 >> 6);
    const int b0 = n0 & 63;
    const int bg = b0 >> 4;
    const int bi = b0 & 15;
    #pragma unroll
    for (int i = 0; i < 8; i++) {
        int r = rt + r0 + i;
        int gate = r >> 9, col = r & 511;
        int cb = col >> 4, cloc = col & 15;
        float bi_f = bias[r];
        float2 p0 = unpack2(acc[i][0]);
        float2 p1 = unpack2(acc[i][1]);
        float2 p2 = unpack2(acc[i][2]);
        float2 p3 = unpack2(acc[i][3]);
        float* dst = g_zx + (((size_t)t * 32 + cb) * 4 + bg) * 1024
                   + (gate * 16 + cloc) * 16 + bi;
        *(float4*)dst       = make_float4(p0.x + bi_f, p0.y + bi_f, p1.x + bi_f, p1.y + bi_f);
        *(float4*)(dst + 4) = make_float4(p2.x + bi_f, p2.y + bi_f, p3.x + bi_f, p3.y + bi_f);
    }
}

// ============================================================================
// Phase 3: barrier-free persistent recurrence. 4 groups x 32 CTAs.
// Dataflow flags per (group, colblock); h read directly from L2 (ld.cg).
// ============================================================================
#define P3_NCTA 128
#define WS_PAD 516
#define OFF_ZSP  (64 * WS_PAD * 4)           // 132096
#define OFF_ZXS  (OFF_ZSP + 32768)           // 164864
#define OFF_MBAR (OFF_ZXS + 8192)            // 173056
#define SM_BYTES (OFF_MBAR + 32)             // 173088

__global__ __launch_bounds__(256) void qlstm_recur(float* __restrict__ out, int out_size) {
    extern __shared__ unsigned char smraw[];
    float* Wsf = (float*)smraw;                     // [64][516]
    float* zsp = (float*)(smraw + OFF_ZSP);         // [8 ks][64 r][16 b]
    float* zxs = (float*)(smraw + OFF_ZXS);         // [2][64 r][16 b]
    u64*   mbars = (u64*)(smraw + OFF_MBAR);        // 2 zx mbars

    const int tid = threadIdx.x;
    const int bc  = blockIdx.x;
    const int bg  = bc >> 5;                 // batch group 0..3
    const int cb  = bc & 31;                 // col block 0..31
    const int c0  = cb * 16;
    const unsigned mb_zx0 = smem_u32(&mbars[0]);

    if (tid == 0) {
        mbar_init(smem_u32(&mbars[0]), 1);
        mbar_init(smem_u32(&mbars[1]), 1);
    }
    __syncthreads();
    fence_proxy_async_cta();
    __syncthreads();

    // load weight slice: 64 rows (gate*16+cloc) x 512 k
    #pragma unroll
    for (int u = 0; u < 32; u++) {
        int idx = tid + u * 256;             // float4 slots
        int lr = idx >> 7, kq = (idx & 127) << 2;
        int gate = lr >> 4, cloc = lr & 15;
        int gr = gate * 512 + c0 + cloc;
        *(float4*)&Wsf[lr * WS_PAD + kq] =
            *(const float4*)(g_W + (size_t)gr * KTOT + 512 + kq);
    }

    // issue zx[0] (one 4KB contiguous slice)
    const size_t zx_cta = ((size_t)cb * 4 + bg) * 1024;
    if (tid == 0) {
        mbar_expect_tx(mb_zx0, 4096);
        bulk_g2s(smem_u32(zxs), g_zx + zx_cta, 4096, mb_zx0);
    }

    const int ep_c = tid >> 4;               // 0..15 local col
    const int ep_b = tid & 15;               // 0..15 local batch
    float creg = 0.0f, hlast = 0.0f;

    const int ks    = tid >> 5;              // warp k-slice (64 k)
    const int lane  = tid & 31;
    const int rq    = lane >> 2;             // rows rq, rq+8, ..., rq+56
    const int pq    = lane & 3;              // b offset pq*4
    const int kbase = ks * 64;
    const unsigned* myflag = &g_flag[bg][4 * ks + (lane & 3)][0];
    const float* wb = Wsf + rq * WS_PAD + kbase;

    for (int s = 0; s < TT; s++) {
        if (tid == 0 && s + 1 < TT) {
            unsigned mz = mb_zx0 + ((s + 1) & 1) * 8;
            mbar_expect_tx(mz, 4096);
            bulk_g2s(smem_u32(zxs + ((s + 1) & 1) * 1024),
                     g_zx + (size_t)(s + 1) * 131072 + zx_cta, 4096, mz);
        }

        // wait for this warp's 4 source h slices (lanes 0-3 poll in parallel)
        if (s > 0) {
            unsigned target = (unsigned)s;
            for (;;) {
                unsigned v = (lane < 4) ? ld_acq(myflag) : 0xFFFFFFFFu;
                if (__all_sync(0xFFFFFFFFu, v >= target)) break;
                __nanosleep(32);
            }
        }

        u64 acc[8][2];
        #pragma unroll
        for (int j = 0; j < 8; j++) { acc[j][0] = 0ULL; acc[j][1] = 0ULL; }

        const float* hgl = &g_hG[bg][s & 1][0] + kbase * 16 + pq * 4;

        #pragma unroll 2
        for (int kb = 0; kb < 16; kb++) {
            ulonglong2 hq[4];
            #pragma unroll
            for (int kk = 0; kk < 4; kk++)
                hq[kk] = ldcg_u64x2(hgl + (kb * 4 + kk) * 16);
            #pragma unroll
            for (int j = 0; j < 8; j++) {
                float4 wv = *(const float4*)(wb + j * 8 * WS_PAD + kb * 4);
                u64 w0 = pack2(wv.x, wv.x), w1 = pack2(wv.y, wv.y);
                u64 w2 = pack2(wv.z, wv.z), w3 = pack2(wv.w, wv.w);
                fma2(acc[j][0], w0, hq[0].x); fma2(acc[j][1], w0, hq[0].y);
                fma2(acc[j][0], w1, hq[1].x); fma2(acc[j][1], w1, hq[1].y);
                fma2(acc[j][0], w2, hq[2].x); fma2(acc[j][1], w2, hq[2].y);
                fma2(acc[j][0], w3, hq[3].x); fma2(acc[j][1], w3, hq[3].y);
            }
        }

        // k-split partials
        #pragma unroll
        for (int j = 0; j < 8; j++) {
            int row = rq + j * 8;
            float2 a = unpack2(acc[j][0]);
            float2 c2 = unpack2(acc[j][1]);
            *(float4*)&zsp[(ks * 64 + row) * 16 + pq * 4] =
                make_float4(a.x, a.y, c2.x, c2.y);
        }
        __syncthreads();

        // epilogue: thread (ep_c, ep_b)
        mbar_wait(mb_zx0 + (s & 1) * 8, (s >> 1) & 1);
        float z[4];
        #pragma unroll
        for (int gi = 0; gi < 4; gi++) {
            int row = gi * 16 + ep_c;
            float ssum = zxs[(s & 1) * 1024 + row * 16 + ep_b];
            #pragma unroll
            for (int q = 0; q < 8; q++)
                ssum += zsp[(q * 64 + row) * 16 + ep_b];
            z[gi] = ssum;
        }
        float fg = sigf(z[0]), ig = sigf(z[1]), ug = tanhf(z[2]), og = sigf(z[3]);
        creg = fg * creg + ig * ug;
        float hv = og * tanhf(creg);
        hlast = hv;
        // publish h (coalesced 1KB) + out scratch (coalesced 1KB)
        g_hG[bg][(s + 1) & 1][(c0 + ep_c) * 16 + ep_b] = hv;
        g_outs[(((size_t)s * 4 + bg) * 32 + cb) * 256 + ep_c * 16 + ep_b] = hv;
        __syncthreads();
        if (tid == 0) {
            __threadfence();
            *(volatile unsigned*)&g_flag[bg][cb][0] = (unsigned)(s + 1);
        }
    }

    size_t TBH = (size_t)TT * BB * HH;
    if ((size_t)out_size >= TBH + 2 * (size_t)BB * HH) {
        size_t bglob = (size_t)bg * 16 + ep_b;
        out[TBH + bglob * HH + c0 + ep_c] = hlast;
        out[TBH + (size_t)BB * HH + bglob * HH + c0 + ep_c] = creg;
    }
}

// ============================================================================
// Phase 4: transpose out scratch -> out[t][b][h]
// ============================================================================
__global__ __launch_bounds__(128) void qlstm_transpose(float* __restrict__ out) {
    __shared__ float tile[4 * 272];          // [bg][c*17 + lb]
    const int t  = blockIdx.x;
    const int cb = blockIdx.y;
    const int tid = threadIdx.x;

    #pragma unroll
    for (int u = 0; u < 8; u++) {
        int idx = tid + u * 128;             // 0..1023
        int bg = idx >> 8, r = idx & 255;    // r = c*16 + lb
        int c = r >> 4, lb = r & 15;
        tile[bg * 272 + c * 17 + lb] =
            g_outs[(((size_t)t * 4 + bg) * 32 + cb) * 256 + r];
    }
    __syncthreads();
    #pragma unroll
    for (int u = 0; u < 8; u++) {
        int idx = tid + u * 128;             // 0..1023
        int b = idx >> 4, c = idx & 15;
        int bg = b >> 4, lb = b & 15;
        out[((size_t)t * 64 + b) * 512 + cb * 16 + c] = tile[bg * 272 + c * 17 + lb];
    }
}

extern "C" void kernel_launch(void* const* d_in, const int* in_sizes, int n_in,
                              void* d_out, int out_size) {
    const float* X  = (const float*)d_in[0];
    const float* v  = (const float*)d_in[1];
    const float* g  = (const float*)d_in[2];
    const float* b  = (const float*)d_in[3];
    float* out = (float*)d_out;

    cudaFuncSetAttribute(qlstm_recur, cudaFuncAttributeMaxDynamicSharedMemorySize, SM_BYTES);

    qlstm_wnorm<<<GG, 256>>>(v, g);
    qlstm_init<<<32, 256>>>();
    qlstm_gemm_x<<<dim3(GG / 128, TT / 2), 256>>>(X, b);
    qlstm_recur<<<P3_NCTA, 256, SM_BYTES>>>(out, out_size);
    qlstm_transpose<<<dim3(TT, 32), 128>>>(out);
}

// round 11
// speedup vs baseline: 1.1703x; 1.1703x over previous
#include <cuda_runtime.h>
#include <math.h>
#include <stdint.h>

#define TT 512
#define BB 64
#define DD 512
#define HH 512
#define GG 2048
#define KTOT 1024
#define P3_NCTA 128

typedef unsigned long long u64;

// ---------------- device scratch ----------------
__device__ float g_W[(size_t)GG * KTOT];        // 8 MB normalized weights
__device__ float g_zx[(size_t)TT * GG * BB];    // 256 MB x-projection (+bias)
__device__ float g_h[2][(size_t)HH * BB];       // h double buffer, [col][b]
__device__ unsigned g_flagv[P3_NCTA][32];       // per-CTA step flags (128B lines)

// ---------------- f32x2 helpers ----------------
__device__ __forceinline__ u64 pack2(float x, float y) {
    u64 r; asm("mov.b64 %0, {%1, %2};" : "=l"(r) : "f"(x), "f"(y)); return r;
}
__device__ __forceinline__ void fma2(u64& d, u64 a, u64 b) {
    asm("fma.rn.f32x2 %0, %1, %2, %0;" : "+l"(d) : "l"(a), "l"(b));
}
__device__ __forceinline__ float2 unpack2(u64 v) {
    float2 f; asm("mov.b64 {%0, %1}, %2;" : "=f"(f.x), "=f"(f.y) : "l"(v)); return f;
}

// ---------------- cp.async (L2-only) ----------------
__device__ __forceinline__ void cp_async16(void* smem_dst, const void* gsrc) {
    unsigned s = (unsigned)__cvta_generic_to_shared(smem_dst);
    asm volatile("cp.async.cg.shared.global [%0], [%1], 16;" :: "r"(s), "l"(gsrc));
}
#define CP_COMMIT() asm volatile("cp.async.commit_group;" ::: "memory")
#define CP_WAIT(n)  asm volatile("cp.async.wait_group %0;" :: "n"(n) : "memory")

__device__ __forceinline__ unsigned ld_acq(const unsigned* p) {
    unsigned v;
    asm volatile("ld.acquire.gpu.u32 %0, [%1];" : "=r"(v) : "l"(p) : "memory");
    return v;
}

__device__ __forceinline__ float sigf(float x) { return 1.0f / (1.0f + expf(-x)); }

// ============================================================================
// Phase 0: per-replay init — zero flags + h buffer 0
// ============================================================================
__global__ __launch_bounds__(256) void qlstm_init() {
    int tid = blockIdx.x * 256 + threadIdx.x;    // grid 128 x 256 = 32768
    ((float*)g_h)[tid] = 0.0f;                   // zeroes g_h[0] exactly
    if (tid < P3_NCTA * 32) ((unsigned*)g_flagv)[tid] = 0u;
}

// ============================================================================
// Phase 1: weight norm
// ============================================================================
__global__ __launch_bounds__(256) void qlstm_wnorm(const float* __restrict__ v,
                                                   const float* __restrict__ g) {
    int r = blockIdx.x;
    const float* vr = v + (size_t)r * KTOT;
    float s = 0.0f;
    for (int k = threadIdx.x; k < KTOT; k += 256) { float x = vr[k]; s += x * x; }
    __shared__ float red[256];
    red[threadIdx.x] = s;
    __syncthreads();
    for (int off = 128; off > 0; off >>= 1) {
        if (threadIdx.x < off) red[threadIdx.x] += red[threadIdx.x + off];
        __syncthreads();
    }
    float scale = g[r] * rsqrtf(red[0]);
    for (int k = threadIdx.x; k < KTOT; k += 256)
        g_W[(size_t)r * KTOT + k] = vr[k] * scale;
}

// ============================================================================
// Phase 2: zx = X @ Wx^T + bias.  CTA 128r x 128n, thread tile 8r x 8n.
// A stored smem-duplicated (w,w): rg-broadcast makes the dup crossbar-free
// and removes the per-kk pack2 movs from the inner loop.
// ============================================================================
#define ASD_PAD 132
#define BSS_PAD 132

__global__ __launch_bounds__(256) void qlstm_gemm_x(const float* __restrict__ X,
                                                    const float* __restrict__ bias) {
    __shared__ u64   Asd[16 * ASD_PAD];   // [k][r] dup pairs (16.9KB)
    __shared__ float Bs[16 * BSS_PAD];    // [k][n]

    const int rt  = blockIdx.x * 128;
    const int nt  = blockIdx.y * 128;
    const int tid = threadIdx.x;
    const int rg  = tid >> 4;
    const int ng  = tid & 15;
    const int r0  = rg * 8;
    const int n0  = ng * 8;

    u64 acc[8][4];
    #pragma unroll
    for (int i = 0; i < 8; i++)
        #pragma unroll
        for (int j = 0; j < 4; j++) acc[i][j] = 0ULL;

    for (int kt = 0; kt < DD; kt += 16) {
        __syncthreads();
        #pragma unroll
        for (int u = 0; u < 2; u++) {
            int idx = tid + u * 256;
            int r = idx >> 2, kq = (idx & 3) << 2;
            float4 va = *(const float4*)(g_W + (size_t)(rt + r) * KTOT + kt + kq);
            Asd[(kq + 0) * ASD_PAD + r] = pack2(va.x, va.x);
            Asd[(kq + 1) * ASD_PAD + r] = pack2(va.y, va.y);
            Asd[(kq + 2) * ASD_PAD + r] = pack2(va.z, va.z);
            Asd[(kq + 3) * ASD_PAD + r] = pack2(va.w, va.w);
        }
        #pragma unroll
        for (int u = 0; u < 2; u++) {
            int idx = tid + u * 256;
            int n = idx >> 2, kq = (idx & 3) << 2;
            float4 vb = *(const float4*)(X + (size_t)(nt + n) * DD + kt + kq);
            Bs[(kq + 0) * BSS_PAD + n] = vb.x;
            Bs[(kq + 1) * BSS_PAD + n] = vb.y;
            Bs[(kq + 2) * BSS_PAD + n] = vb.z;
            Bs[(kq + 3) * BSS_PAD + n] = vb.w;
        }
        __syncthreads();

        #pragma unroll
        for (int kk = 0; kk < 16; kk++) {
            ulonglong2 b01 = *(const ulonglong2*)&Bs[kk * BSS_PAD + n0];
            ulonglong2 b23 = *(const ulonglong2*)&Bs[kk * BSS_PAD + n0 + 4];
            ulonglong2 a01 = *(const ulonglong2*)&Asd[kk * ASD_PAD + r0];
            ulonglong2 a23 = *(const ulonglong2*)&Asd[kk * ASD_PAD + r0 + 2];
            ulonglong2 a45 = *(const ulonglong2*)&Asd[kk * ASD_PAD + r0 + 4];
            ulonglong2 a67 = *(const ulonglong2*)&Asd[kk * ASD_PAD + r0 + 6];
            u64 wv[8] = {a01.x, a01.y, a23.x, a23.y, a45.x, a45.y, a67.x, a67.y};
            #pragma unroll
            for (int i = 0; i < 8; i++) {
                fma2(acc[i][0], wv[i], b01.x); fma2(acc[i][1], wv[i], b01.y);
                fma2(acc[i][2], wv[i], b23.x); fma2(acc[i][3], wv[i], b23.y);
            }
        }
    }

    const int t  = blockIdx.y * 2 + (n0 >> 6);
    const int b0 = n0 & 63;
    #pragma unroll
    for (int i = 0; i < 8; i++) {
        int r = rt + r0 + i;
        float bi = bias[r];
        float2 p0 = unpack2(acc[i][0]);
        float2 p1 = unpack2(acc[i][1]);
        float2 p2 = unpack2(acc[i][2]);
        float2 p3 = unpack2(acc[i][3]);
        float* dst = g_zx + ((size_t)t * GG + r) * BB + b0;
        *(float4*)dst       = make_float4(p0.x + bi, p0.y + bi, p1.x + bi, p1.y + bi);
        *(float4*)(dst + 4) = make_float4(p2.x + bi, p2.y + bi, p3.x + bi, p3.y + bi);
    }
}

// ============================================================================
// Phase 3: persistent recurrence. 128 CTAs x 256 thr = 8 warps (winner core).
// NEW: per-CTA flag barrier (no atomic serialization), zx off the wait path
// via separate cp.async groups + wait_group 1, out store after flag publish.
// ============================================================================
#define WS_PAD 516
#define OFF_HS  (16 * WS_PAD * 4)
#define OFF_ZSP (OFF_HS + 131072)
#define OFF_ZXS (OFF_ZSP + 32768)
#define SM_BYTES (OFF_ZXS + 8192)

__global__ __launch_bounds__(256) void qlstm_recur(float* __restrict__ out, int out_size) {
    extern __shared__ unsigned char smraw[];
    float* Wsf = (float*)smraw;                     // [16][516] non-dup
    float* hs  = (float*)(smraw + OFF_HS);          // [512][64]
    float* zsp = (float*)(smraw + OFF_ZSP);         // [8 ks][16][64]
    float* zxs = (float*)(smraw + OFF_ZXS);         // [2][16][64]

    const int tid = threadIdx.x;
    const int bc  = blockIdx.x;
    const int c0  = bc * 4;

    // load weight slice (non-duplicated)
    #pragma unroll
    for (int u = 0; u < 32; u++) {
        int idx = tid + u * 256;
        int lr = idx >> 9, k = idx & 511;
        int gr = (lr >> 2) * 512 + c0 + (lr & 3);
        Wsf[lr * WS_PAD + k] = g_W[(size_t)gr * KTOT + 512 + k];
    }

    const int pf_lr = tid >> 4;
    const int pf_b  = (tid & 15) * 4;
    const int pf_gr = (pf_lr >> 2) * 512 + c0 + (pf_lr & 3);

    // prefetch zx[0] as its own group (Z0)
    cp_async16(zxs + pf_lr * 64 + pf_b, g_zx + (size_t)pf_gr * BB + pf_b);
    CP_COMMIT();

    const int ep_j = tid >> 6, ep_b = tid & 63;
    float creg = 0.0f, hlast = 0.0f;

    const int ks    = tid >> 5;
    const int lane  = tid & 31;
    const int rgi   = (tid >> 4) & 1;
    const int b0    = (tid & 15) * 4;
    const int kbase = ks * 64;

    for (int s = 0; s < TT; s++) {
        // ---- flag barrier wait: peers' h(s) published (parallel flag lines)
        if (tid < P3_NCTA) {
            const unsigned* fl = &g_flagv[tid][0];
            while (ld_acq(fl) < (unsigned)s) { }
        }
        __syncthreads();

        // ---- stage own 16KB h slice (group H_s)
        {
            const float* src = g_h[s & 1] + kbase * 64;
            float* dst = hs + kbase * 64;
            #pragma unroll
            for (int u = 0; u < 32; u++) {
                int idx = lane + u * 32;
                cp_async16(dst + idx * 4, src + idx * 4);
            }
            CP_COMMIT();
        }
        // ---- zx prefetch for s+1 (group Z_{s+1}; clamped so groups stay uniform)
        {
            int sn = (s + 1 < TT) ? s + 1 : TT - 1;
            cp_async16(zxs + ((s + 1) & 1) * 1024 + pf_lr * 64 + pf_b,
                       g_zx + ((size_t)sn * GG + pf_gr) * BB + pf_b);
            CP_COMMIT();
        }
        // wait for H_s (and all older, incl. Z_s); Z_{s+1} may stay in flight
        CP_WAIT(1);
        __syncwarp();

        u64 acc[8][2];
        #pragma unroll
        for (int r = 0; r < 8; r++) { acc[r][0] = 0ULL; acc[r][1] = 0ULL; }

        const float* hbase = hs + kbase * 64 + b0;
        const float* wbase = Wsf + rgi * WS_PAD + kbase;

        #pragma unroll 4
        for (int kb = 0; kb < 16; kb++) {
            ulonglong2 hq[4];
            #pragma unroll
            for (int j = 0; j < 4; j++)
                hq[j] = *(const ulonglong2*)(hbase + (kb * 4 + j) * 64);
            #pragma unroll
            for (int rr = 0; rr < 8; rr++) {
                float4 wv = *(const float4*)(wbase + rr * 2 * WS_PAD + kb * 4);
                u64 w0 = pack2(wv.x, wv.x), w1 = pack2(wv.y, wv.y);
                u64 w2 = pack2(wv.z, wv.z), w3 = pack2(wv.w, wv.w);
                fma2(acc[rr][0], w0, hq[0].x); fma2(acc[rr][1], w0, hq[0].y);
                fma2(acc[rr][0], w1, hq[1].x); fma2(acc[rr][1], w1, hq[1].y);
                fma2(acc[rr][0], w2, hq[2].x); fma2(acc[rr][1], w2, hq[2].y);
                fma2(acc[rr][0], w3, hq[3].x); fma2(acc[rr][1], w3, hq[3].y);
            }
        }

        #pragma unroll
        for (int rr = 0; rr < 8; rr++) {
            int lr = rr * 2 + rgi;
            float2 a = unpack2(acc[rr][0]);
            float2 c2 = unpack2(acc[rr][1]);
            *(float4*)&zsp[(ks * 16 + lr) * 64 + b0] = make_float4(a.x, a.y, c2.x, c2.y);
        }
        __syncthreads();

        // gate epilogue (zx for this step completed: older group than H_s)
        float z[4];
        #pragma unroll
        for (int gi = 0; gi < 4; gi++) {
            int row = gi * 4 + ep_j;
            float ssum = zxs[(s & 1) * 1024 + row * 64 + ep_b];
            #pragma unroll
            for (int q = 0; q < 8; q++)
                ssum += zsp[(q * 16 + row) * 64 + ep_b];
            z[gi] = ssum;
        }
        float fg = sigf(z[0]), ig = sigf(z[1]), ug = tanhf(z[2]), og = sigf(z[3]);
        creg = fg * creg + ig * ug;
        float hv = og * tanhf(creg);
        hlast = hv;
        // publish h (coalesced) BEFORE the flag
        g_h[(s + 1) & 1][(size_t)(c0 + ep_j) * BB + ep_b] = hv;
        __syncthreads();
        if (tid == 0) {
            __threadfence();
            *(volatile unsigned*)&g_flagv[bc][0] = (unsigned)(s + 1);
        }
        // out store AFTER flag publish: off the fence path, overlaps propagation
        out[((size_t)s * BB + ep_b) * HH + c0 + ep_j] = hv;
    }

    size_t TBH = (size_t)TT * BB * HH;
    if ((size_t)out_size >= TBH + 2 * (size_t)BB * HH) {
        out[TBH + (size_t)ep_b * HH + c0 + ep_j] = hlast;
        out[TBH + (size_t)BB * HH + (size_t)ep_b * HH + c0 + ep_j] = creg;
    }
}

extern "C" void kernel_launch(void* const* d_in, const int* in_sizes, int n_in,
                              void* d_out, int out_size) {
    const float* X  = (const float*)d_in[0];
    const float* v  = (const float*)d_in[1];
    const float* g  = (const float*)d_in[2];
    const float* b  = (const float*)d_in[3];
    float* out = (float*)d_out;

    cudaFuncSetAttribute(qlstm_recur, cudaFuncAttributeMaxDynamicSharedMemorySize, SM_BYTES);

    qlstm_wnorm<<<GG, 256>>>(v, g);
    qlstm_init<<<P3_NCTA, 256>>>();
    qlstm_gemm_x<<<dim3(GG / 128, TT / 2), 256>>>(X, b);
    qlstm_recur<<<P3_NCTA, 256, SM_BYTES>>>(out, out_size);
}

// round 12
// speedup vs baseline: 1.3499x; 1.1535x over previous
#include <cuda_runtime.h>
#include <math.h>
#include <stdint.h>

#define TT 512
#define BB 64
#define DD 512
#define HH 512
#define GG 2048
#define KTOT 1024
#define P3_NCTA 128

typedef unsigned long long u64;

// ---------------- device scratch ----------------
__device__ float g_W[(size_t)GG * KTOT];        // 8 MB normalized weights
__device__ float g_Xt[(size_t)TT * DD * BB];    // 64 MB X transposed [t][d][b]
__device__ float g_h[2][(size_t)HH * BB];       // h double buffer, [col][b]
__device__ unsigned g_flagv[P3_NCTA][32];       // per-CTA step flags (128B lines)

// ---------------- f32x2 helpers ----------------
__device__ __forceinline__ u64 pack2(float x, float y) {
    u64 r; asm("mov.b64 %0, {%1, %2};" : "=l"(r) : "f"(x), "f"(y)); return r;
}
__device__ __forceinline__ void fma2(u64& d, u64 a, u64 b) {
    asm("fma.rn.f32x2 %0, %1, %2, %0;" : "+l"(d) : "l"(a), "l"(b));
}
__device__ __forceinline__ float2 unpack2(u64 v) {
    float2 f; asm("mov.b64 {%0, %1}, %2;" : "=f"(f.x), "=f"(f.y) : "l"(v)); return f;
}

// ---------------- cp.async (L2-only) ----------------
__device__ __forceinline__ void cp_async16(void* smem_dst, const void* gsrc) {
    unsigned s = (unsigned)__cvta_generic_to_shared(smem_dst);
    asm volatile("cp.async.cg.shared.global [%0], [%1], 16;" :: "r"(s), "l"(gsrc));
}
#define CP_COMMIT() asm volatile("cp.async.commit_group;" ::: "memory")
#define CP_WAIT(n)  asm volatile("cp.async.wait_group %0;" :: "n"(n) : "memory")

__device__ __forceinline__ unsigned ld_acq(const unsigned* p) {
    unsigned v;
    asm volatile("ld.acquire.gpu.u32 %0, [%1];" : "=r"(v) : "l"(p) : "memory");
    return v;
}
// L2-cached read-only 16B load for X
__device__ __forceinline__ ulonglong2 ldg_nc16(const void* p) {
    ulonglong2 r;
    asm volatile("ld.global.nc.v2.u64 {%0, %1}, [%2];" : "=l"(r.x), "=l"(r.y) : "l"(p));
    return r;
}

__device__ __forceinline__ float sigf(float x) { return 1.0f / (1.0f + expf(-x)); }

// ============================================================================
// Phase 0: per-replay init — zero flags + h buffer 0
// ============================================================================
__global__ __launch_bounds__(256) void qlstm_init() {
    int tid = blockIdx.x * 256 + threadIdx.x;    // grid 128 x 256 = 32768
    ((float*)g_h)[tid] = 0.0f;                   // zeroes g_h[0] exactly
    if (tid < P3_NCTA * 32) ((unsigned*)g_flagv)[tid] = 0u;
}

// ============================================================================
// Phase 1: weight norm
// ============================================================================
__global__ __launch_bounds__(256) void qlstm_wnorm(const float* __restrict__ v,
                                                   const float* __restrict__ g) {
    int r = blockIdx.x;
    const float* vr = v + (size_t)r * KTOT;
    float s = 0.0f;
    for (int k = threadIdx.x; k < KTOT; k += 256) { float x = vr[k]; s += x * x; }
    __shared__ float red[256];
    red[threadIdx.x] = s;
    __syncthreads();
    for (int off = 128; off > 0; off >>= 1) {
        if (threadIdx.x < off) red[threadIdx.x] += red[threadIdx.x + off];
        __syncthreads();
    }
    float scale = g[r] * rsqrtf(red[0]);
    for (int k = threadIdx.x; k < KTOT; k += 256)
        g_W[(size_t)r * KTOT + k] = vr[k] * scale;
}

// ============================================================================
// Phase 1.5: transpose X[t][b][d] -> Xt[t][d][b]
// ============================================================================
__global__ __launch_bounds__(256) void qlstm_xpose(const float* __restrict__ X) {
    __shared__ float tile[64 * 65];
    const int t  = blockIdx.x;
    const int d0 = blockIdx.y * 64;
    const int dx = threadIdx.x & 63, bq = threadIdx.x >> 6;
    #pragma unroll
    for (int i = 0; i < 16; i++) {
        int b = bq + i * 4;
        tile[dx * 65 + b] = X[((size_t)t * BB + b) * DD + d0 + dx];
    }
    __syncthreads();
    const int bx = threadIdx.x & 63, dq = threadIdx.x >> 6;
    #pragma unroll
    for (int i = 0; i < 16; i++) {
        int d = dq + i * 4;
        g_Xt[((size_t)t * DD + d0 + d) * BB + bx] = tile[d * 65 + bx];
    }
}

// ============================================================================
// Phase 3: FUSED persistent recurrence.
// Per step: x-part (Wx . x(s), no dependency) computes first, filling the
// wait window; then per-warp producer-flag wait, h staging, h-part accumulate.
// ============================================================================
#define WS_PAD 516
#define OFF_WX  (16 * WS_PAD * 4)            // 33024
#define OFF_HS  (OFF_WX + 16 * WS_PAD * 4)   // 66048
#define OFF_ZSP (OFF_HS + 131072)            // 197120
#define SM_BYTES (OFF_ZSP + 32768)           // 229888

__global__ __launch_bounds__(256) void qlstm_recur(const float* __restrict__ bias,
                                                   float* __restrict__ out, int out_size) {
    extern __shared__ unsigned char smraw[];
    float* Whs = (float*)smraw;                     // [16][516] recurrent W
    float* Wxs = (float*)(smraw + OFF_WX);          // [16][516] input W
    float* hs  = (float*)(smraw + OFF_HS);          // [512][64]
    float* zsp = (float*)(smraw + OFF_ZSP);         // [8 ks][16][64]

    const int tid = threadIdx.x;
    const int bc  = blockIdx.x;
    const int c0  = bc * 4;

    // load both weight slices
    #pragma unroll
    for (int u = 0; u < 32; u++) {
        int idx = tid + u * 256;
        int lr = idx >> 9, k = idx & 511;
        int gr = (lr >> 2) * 512 + c0 + (lr & 3);
        Whs[lr * WS_PAD + k] = g_W[(size_t)gr * KTOT + 512 + k];
        Wxs[lr * WS_PAD + k] = g_W[(size_t)gr * KTOT + k];
    }

    const int ep_j = tid >> 6, ep_b = tid & 63;
    float bz[4];
    #pragma unroll
    for (int gi = 0; gi < 4; gi++) bz[gi] = bias[gi * 512 + c0 + ep_j];
    float creg = 0.0f, hlast = 0.0f;

    const int ks    = tid >> 5;              // warp k-slice (64 of 512)
    const int lane  = tid & 31;
    const int rgi   = (tid >> 4) & 1;
    const int b0    = (tid & 15) * 4;
    const int kbase = ks * 64;
    const unsigned* myflag = &g_flagv[ks * 16 + (lane & 15)][0];
    const float* whb = Whs + rgi * WS_PAD + kbase;
    const float* wxb = Wxs + rgi * WS_PAD + kbase;
    __syncthreads();

    for (int s = 0; s < TT; s++) {
        u64 acc[8][2];
        #pragma unroll
        for (int r = 0; r < 8; r++) { acc[r][0] = 0ULL; acc[r][1] = 0ULL; }

        // ---- x-part: no dependency; fills the wait window ----
        {
            const float* xb = g_Xt + ((size_t)s * DD + kbase) * BB + b0;
            ulonglong2 xq[2][4];
            #pragma unroll
            for (int j = 0; j < 4; j++) xq[0][j] = ldg_nc16(xb + j * 64);
            #pragma unroll 2
            for (int kb = 0; kb < 16; kb++) {
                int cur = kb & 1;
                if (kb < 15) {
                    #pragma unroll
                    for (int j = 0; j < 4; j++)
                        xq[cur ^ 1][j] = ldg_nc16(xb + ((kb + 1) * 4 + j) * 64);
                }
                #pragma unroll
                for (int rr = 0; rr < 8; rr++) {
                    float4 wv = *(const float4*)(wxb + rr * 2 * WS_PAD + kb * 4);
                    u64 w0 = pack2(wv.x, wv.x), w1 = pack2(wv.y, wv.y);
                    u64 w2 = pack2(wv.z, wv.z), w3 = pack2(wv.w, wv.w);
                    fma2(acc[rr][0], w0, xq[cur][0].x); fma2(acc[rr][1], w0, xq[cur][0].y);
                    fma2(acc[rr][0], w1, xq[cur][1].x); fma2(acc[rr][1], w1, xq[cur][1].y);
                    fma2(acc[rr][0], w2, xq[cur][2].x); fma2(acc[rr][1], w2, xq[cur][2].y);
                    fma2(acc[rr][0], w3, xq[cur][3].x); fma2(acc[rr][1], w3, xq[cur][3].y);
                }
            }
        }

        // ---- per-warp flag wait: the 16 producers of my h k-slice ----
        if (s > 0) {
            for (;;) {
                unsigned v = ld_acq(myflag);
                if (__all_sync(0xFFFFFFFFu, v >= (unsigned)s)) break;
                __nanosleep(20);
            }
        }

        // ---- stage own 16KB h slice ----
        {
            const float* src = g_h[s & 1] + kbase * 64;
            float* dst = hs + kbase * 64;
            #pragma unroll
            for (int u = 0; u < 32; u++) {
                int idx = lane + u * 32;
                cp_async16(dst + idx * 4, src + idx * 4);
            }
            CP_COMMIT();
            CP_WAIT(0);
            __syncwarp();
        }

        // ---- h-part: accumulate into same registers ----
        {
            const float* hbase = hs + kbase * 64 + b0;
            #pragma unroll 4
            for (int kb = 0; kb < 16; kb++) {
                ulonglong2 hq[4];
                #pragma unroll
                for (int j = 0; j < 4; j++)
                    hq[j] = *(const ulonglong2*)(hbase + (kb * 4 + j) * 64);
                #pragma unroll
                for (int rr = 0; rr < 8; rr++) {
                    float4 wv = *(const float4*)(whb + rr * 2 * WS_PAD + kb * 4);
                    u64 w0 = pack2(wv.x, wv.x), w1 = pack2(wv.y, wv.y);
                    u64 w2 = pack2(wv.z, wv.z), w3 = pack2(wv.w, wv.w);
                    fma2(acc[rr][0], w0, hq[0].x); fma2(acc[rr][1], w0, hq[0].y);
                    fma2(acc[rr][0], w1, hq[1].x); fma2(acc[rr][1], w1, hq[1].y);
                    fma2(acc[rr][0], w2, hq[2].x); fma2(acc[rr][1], w2, hq[2].y);
                    fma2(acc[rr][0], w3, hq[3].x); fma2(acc[rr][1], w3, hq[3].y);
                }
            }
        }

        // ---- k-split partials ----
        #pragma unroll
        for (int rr = 0; rr < 8; rr++) {
            int lr = rr * 2 + rgi;
            float2 a = unpack2(acc[rr][0]);
            float2 c2 = unpack2(acc[rr][1]);
            *(float4*)&zsp[(ks * 16 + lr) * 64 + b0] = make_float4(a.x, a.y, c2.x, c2.y);
        }
        __syncthreads();

        // ---- gate epilogue ----
        float z[4];
        #pragma unroll
        for (int gi = 0; gi < 4; gi++) {
            int row = gi * 4 + ep_j;
            float ssum = bz[gi];
            #pragma unroll
            for (int q = 0; q < 8; q++)
                ssum += zsp[(q * 16 + row) * 64 + ep_b];
            z[gi] = ssum;
        }
        float fg = sigf(z[0]), ig = sigf(z[1]), ug = tanhf(z[2]), og = sigf(z[3]);
        creg = fg * creg + ig * ug;
        float hv = og * tanhf(creg);
        hlast = hv;
        g_h[(s + 1) & 1][(size_t)(c0 + ep_j) * BB + ep_b] = hv;
        __syncthreads();
        if (tid == 0) {
            __threadfence();
            *(volatile unsigned*)&g_flagv[bc][0] = (unsigned)(s + 1);
        }
        out[((size_t)s * BB + ep_b) * HH + c0 + ep_j] = hv;
    }

    size_t TBH = (size_t)TT * BB * HH;
    if ((size_t)out_size >= TBH + 2 * (size_t)BB * HH) {
        out[TBH + (size_t)ep_b * HH + c0 + ep_j] = hlast;
        out[TBH + (size_t)BB * HH + (size_t)ep_b * HH + c0 + ep_j] = creg;
    }
}

extern "C" void kernel_launch(void* const* d_in, const int* in_sizes, int n_in,
                              void* d_out, int out_size) {
    const float* X  = (const float*)d_in[0];
    const float* v  = (const float*)d_in[1];
    const float* g  = (const float*)d_in[2];
    const float* b  = (const float*)d_in[3];
    float* out = (float*)d_out;

    cudaFuncSetAttribute(qlstm_recur, cudaFuncAttributeMaxDynamicSharedMemorySize, SM_BYTES);

    qlstm_wnorm<<<GG, 256>>>(v, g);
    qlstm_xpose<<<dim3(TT, DD / 64), 256>>>(X);
    qlstm_init<<<P3_NCTA, 256>>>();
    qlstm_recur<<<P3_NCTA, 256, SM_BYTES>>>(b, out, out_size);
}